// round 9
// baseline (speedup 1.0000x reference)
#include <cuda_runtime.h>
#include <math_constants.h>

// x [B=32, C=256, H=64, W=64] fp32
#define B    32
#define C    256
#define HW   4096
#define W64  64

// ---- k1 tiling (round-3 optimum) ----
#define K1T    128             // threads/block
#define HWT    512             // hw floats per block tile
#define NHWT   (HW / HWT)      // 8
#define CR     64              // channels per block
#define NCR    (C / CR)        // 4
#define CHUNK  4
#define NCHUNK (CR / CHUNK)    // 16
#define RED_PER_B (NCR * NHWT) // 32 CTAs per b; grid 1024 = one wave @7/SM

// ---- scratch (device globals; allocation-free) ----
__device__ float    g_cpart[B * NHWT * C];
__device__ float4   g_pmax[NCR][B * HW / 4];
__device__ float4   g_psum[NCR][B * HW / 4];
__device__ float    g_chw[B * C];
__device__ float4   g_sp4[B * HW / 4];
__device__ unsigned g_cnt[B];        // per-b arrivals (reset by k4 each replay)

// smem: reduce uses 1024 floats; spatial weight tile needs 2*22*72+99=3267
#define POOL_FLOATS 3300

// =====================================================================
// k1: round-3 reduce sweep; then the 5 lowest CTAs of each b finish the
//     weights (1 chw + 4 spatial 16-row tiles) after a per-b counter
//     barrier. Single resident wave -> spin-safe.
// =====================================================================
__global__ __launch_bounds__(K1T, 7) void k1_reduce(const float* __restrict__ x,
                                                    const float* __restrict__ w1d,
                                                    const float* __restrict__ w2d,
                                                    const float* __restrict__ bias)
{
    const int cr   = blockIdx.x;
    const int ht   = blockIdx.y;
    const int b    = blockIdx.z;
    const int tid  = threadIdx.x;
    const int warp = tid >> 5;
    const int lane = tid & 31;

    __shared__ float pool[POOL_FLOATS];
    float (*sbuf)[CHUNK][K1T] = (float (*)[CHUNK][K1T])pool;

    const float4* __restrict__ xp =
        (const float4*)x + ((long)(b * C + cr * CR) * HW + ht * HWT) / 4 + tid;

    float4 mx = make_float4(-CUDART_INF_F, -CUDART_INF_F, -CUDART_INF_F, -CUDART_INF_F);
    float4 sm = make_float4(0.f, 0.f, 0.f, 0.f);

    float4 p[CHUNK];
    #pragma unroll
    for (int j = 0; j < CHUNK; ++j) p[j] = xp[j * (HW / 4)];

    #pragma unroll 2
    for (int ch = 0; ch < NCHUNK; ++ch) {
        float4 v[CHUNK];
        #pragma unroll
        for (int j = 0; j < CHUNK; ++j) v[j] = p[j];

        float (*sb)[K1T] = sbuf[ch & 1];
        #pragma unroll
        for (int j = 0; j < CHUNK; ++j)
            sb[j][tid] = (v[j].x + v[j].y) + (v[j].z + v[j].w);

        if (ch + 1 < NCHUNK) {
            #pragma unroll
            for (int j = 0; j < CHUNK; ++j)
                p[j] = xp[((ch + 1) * CHUNK + j) * (HW / 4)];
        }

        #pragma unroll
        for (int j = 0; j < CHUNK; ++j) {
            mx.x = fmaxf(mx.x, v[j].x); mx.y = fmaxf(mx.y, v[j].y);
            mx.z = fmaxf(mx.z, v[j].z); mx.w = fmaxf(mx.w, v[j].w);
            sm.x += v[j].x; sm.y += v[j].y; sm.z += v[j].z; sm.w += v[j].w;
        }

        __syncthreads();
        float r = (sb[warp][lane]      + sb[warp][lane + 32])
                + (sb[warp][lane + 64] + sb[warp][lane + 96]);
        r += __shfl_xor_sync(0xffffffffu, r, 16);
        r += __shfl_xor_sync(0xffffffffu, r, 8);
        r += __shfl_xor_sync(0xffffffffu, r, 4);
        r += __shfl_xor_sync(0xffffffffu, r, 2);
        r += __shfl_xor_sync(0xffffffffu, r, 1);
        if (lane == 0)
            g_cpart[(b * NHWT + ht) * C + cr * CR + ch * CHUNK + warp] = r;
    }

    const int o = b * (HW / 4) + ht * (HWT / 4) + tid;
    g_pmax[cr][o] = mx;
    g_psum[cr][o] = sm;

    // ---- per-b completion counter; low-5 CTAs take weight roles ----
    __threadfence();
    __syncthreads();
    const int wid = cr * NHWT + ht;     // 0..31 within this b
    if (tid == 0) {
        atomicAdd(&g_cnt[b], 1u);
        if (wid < 5) {
            while (*(volatile unsigned*)&g_cnt[b] < (unsigned)RED_PER_B)
                __nanosleep(64);
            __threadfence();
        }
    }
    if (wid >= 5) return;
    __syncthreads();

    if (wid == 0) {
        // ---- channel weight: mean -> conv1d(5, pad 2) -> sigmoid ----
        float* mean = pool;             // 256 floats
        #pragma unroll
        for (int c = tid; c < C; c += K1T) {
            float acc = 0.f;
            #pragma unroll
            for (int h2 = 0; h2 < NHWT; ++h2)
                acc += g_cpart[(b * NHWT + h2) * C + c];
            mean[c] = acc * (1.0f / (float)HW);
        }
        __syncthreads();
        #pragma unroll
        for (int c = tid; c < C; c += K1T) {
            float y = 0.f;
            #pragma unroll
            for (int k = 0; k < 5; ++k) {
                int cc = c - 2 + k;
                float m = (cc >= 0 && cc < C) ? mean[cc] : 0.f;
                y += w1d[k] * m;
            }
            g_chw[b * C + c] = 1.0f / (1.0f + expf(-y));
        }
    } else {
        // ---- spatial weight tile: rows [r0, r0+16) ----
        const int r0 = (wid - 1) * 16;
        float* smax = pool;                  // [22][72]
        float* savg = pool + 22 * 72;
        float* sw   = pool + 2 * 22 * 72;    // 98 taps + bias at [98]

        for (int i = tid; i < 22 * 70; i += K1T) {
            int rr = i / 70, cc = i % 70;
            int gr = r0 - 3 + rr, gc = cc - 3;
            float mv = 0.f, av = 0.f;
            if (gr >= 0 && gr < W64 && gc >= 0 && gc < W64) {
                int gi = b * HW + gr * W64 + gc;
                mv = -CUDART_INF_F;
                #pragma unroll
                for (int r = 0; r < NCR; ++r) {
                    mv = fmaxf(mv, ((const float*)g_pmax[r])[gi]);
                    av += ((const float*)g_psum[r])[gi];
                }
                av *= (1.0f / (float)C);
            }
            smax[rr * 72 + cc] = mv;
            savg[rr * 72 + cc] = av;
        }
        if (tid < 98) sw[tid] = w2d[tid];
        if (tid == 0) sw[98] = bias[0];
        __syncthreads();

        float* __restrict__ sp = (float*)g_sp4;
        #pragma unroll
        for (int k = 0; k < 8; ++k) {
            int oi   = tid + k * K1T;        // 0..1023
            int orow = oi >> 6;
            int ocol = oi & 63;
            float acc = sw[98];
            #pragma unroll
            for (int kh = 0; kh < 7; ++kh) {
                #pragma unroll
                for (int kw = 0; kw < 7; ++kw) {
                    acc += sw[kh * 7 + kw]      * smax[(orow + kh) * 72 + ocol + kw];
                    acc += sw[49 + kh * 7 + kw] * savg[(orow + kh) * 72 + ocol + kw];
                }
            }
            sp[b * HW + (r0 + orow) * W64 + ocol] = 1.0f / (1.0f + expf(-acc));
        }
    }
}

// =====================================================================
// k4: out = x * (chw[b,c] + sp[b,hw] + 1), reversed traversal + stcs.
//     Block 0 resets the per-b counters for the next graph replay.
// =====================================================================
#define TOTAL4 (B * C * HW / 4)
__global__ __launch_bounds__(256) void k4_scale(const float4* __restrict__ x4,
                                                float4* __restrict__ out4)
{
    if (blockIdx.x == 0 && threadIdx.x < B) g_cnt[threadIdx.x] = 0;

    const int i4  = (TOTAL4 - 1) - (blockIdx.x * 256 + threadIdx.x);
    const int hw4 = i4 & 1023;
    const int bc  = i4 >> 10;
    const int b   = bc >> 8;

    const float  cw = g_chw[bc] + 1.0f;
    const float4 sp = g_sp4[b * 1024 + hw4];
    const float4 v  = x4[i4];

    float4 o;
    o.x = v.x * (cw + sp.x);
    o.y = v.y * (cw + sp.y);
    o.z = v.z * (cw + sp.z);
    o.w = v.w * (cw + sp.w);
    __stcs(&out4[i4], o);
}

// =====================================================================
extern "C" void kernel_launch(void* const* d_in, const int* in_sizes, int n_in,
                              void* d_out, int out_size)
{
    const float* x    = (const float*)d_in[0];  // [32,256,64,64]
    const float* w1d  = (const float*)d_in[1];  // [1,1,5]
    const float* w2d  = (const float*)d_in[2];  // [1,2,7,7]
    const float* bias = (const float*)d_in[3];  // [1]
    float* out = (float*)d_out;

    dim3 g1(NCR, NHWT, B);
    k1_reduce<<<g1, K1T>>>(x, w1d, w2d, bias);
    k4_scale<<<TOTAL4 / 256, 256>>>((const float4*)x, (float4*)out);
}

// round 10
// speedup vs baseline: 1.0338x; 1.0338x over previous
#include <cuda_runtime.h>
#include <math_constants.h>

// x [B=32, C=256, H=64, W=64] fp32
#define B    32
#define C    256
#define HW   4096
#define W64  64

// ---- k1 tiling (round-3 optimum; do not touch) ----
#define K1T    128             // threads/block
#define HWT    512             // hw floats per block tile (128 float4)
#define NHWT   (HW / HWT)      // 8
#define CR     64              // channels per block
#define NCR    (C / CR)        // 4
#define CHUNK  4
#define NCHUNK (CR / CHUNK)    // 16

// ---- scratch (device globals; allocation-free) ----
__device__ float  g_cpart[B * NHWT * C];     // per-(b,c,hw-tile) partial sums
__device__ float4 g_pmax[NCR][B * HW / 4];   // per-c-range max partials
__device__ float4 g_psum[NCR][B * HW / 4];   // per-c-range sum partials
__device__ float  g_chw[B * C];              // channel weight
__device__ float4 g_sp4[B * HW / 4];         // spatial weight

// =====================================================================
// k1: single sweep over x. block=(cr,ht,b), 1024 CTAs.
// Register-prefetched 4-channel chunks; smem transpose for per-c sums.
// =====================================================================
__global__ __launch_bounds__(K1T) void k1_reduce(const float* __restrict__ x)
{
    const int cr   = blockIdx.x;
    const int ht   = blockIdx.y;
    const int b    = blockIdx.z;
    const int tid  = threadIdx.x;
    const int warp = tid >> 5;
    const int lane = tid & 31;

    __shared__ float sbuf[2][CHUNK][K1T];

    const float4* __restrict__ xp =
        (const float4*)x + ((long)(b * C + cr * CR) * HW + ht * HWT) / 4 + tid;

    float4 mx = make_float4(-CUDART_INF_F, -CUDART_INF_F, -CUDART_INF_F, -CUDART_INF_F);
    float4 sm = make_float4(0.f, 0.f, 0.f, 0.f);

    float4 p[CHUNK];
    #pragma unroll
    for (int j = 0; j < CHUNK; ++j) p[j] = xp[j * (HW / 4)];

    #pragma unroll 2
    for (int ch = 0; ch < NCHUNK; ++ch) {
        float4 v[CHUNK];
        #pragma unroll
        for (int j = 0; j < CHUNK; ++j) v[j] = p[j];

        // stage per-thread channel sums, then kick off next chunk's loads
        float (*sb)[K1T] = sbuf[ch & 1];
        #pragma unroll
        for (int j = 0; j < CHUNK; ++j)
            sb[j][tid] = (v[j].x + v[j].y) + (v[j].z + v[j].w);

        if (ch + 1 < NCHUNK) {
            #pragma unroll
            for (int j = 0; j < CHUNK; ++j)
                p[j] = xp[((ch + 1) * CHUNK + j) * (HW / 4)];
        }

        #pragma unroll
        for (int j = 0; j < CHUNK; ++j) {
            mx.x = fmaxf(mx.x, v[j].x); mx.y = fmaxf(mx.y, v[j].y);
            mx.z = fmaxf(mx.z, v[j].z); mx.w = fmaxf(mx.w, v[j].w);
            sm.x += v[j].x; sm.y += v[j].y; sm.z += v[j].z; sm.w += v[j].w;
        }

        __syncthreads();
        // warp w reduces channel ch*4+w over all 128 threads (stride-32: conflict-free)
        float r = (sb[warp][lane]      + sb[warp][lane + 32])
                + (sb[warp][lane + 64] + sb[warp][lane + 96]);
        r += __shfl_xor_sync(0xffffffffu, r, 16);
        r += __shfl_xor_sync(0xffffffffu, r, 8);
        r += __shfl_xor_sync(0xffffffffu, r, 4);
        r += __shfl_xor_sync(0xffffffffu, r, 2);
        r += __shfl_xor_sync(0xffffffffu, r, 1);
        if (lane == 0)
            g_cpart[(b * NHWT + ht) * C + cr * CR + ch * CHUNK + warp] = r;
    }

    const int o = b * (HW / 4) + ht * (HWT / 4) + tid;
    g_pmax[cr][o] = mx;
    g_psum[cr][o] = sm;
}

// =====================================================================
// k23: fused channel-weight (blocks 0..31) and spatial-weight (32..159).
// =====================================================================
#define SMAX_OFF 0
#define SAVG_OFF (22 * 72)
#define SW_OFF   (2 * 22 * 72)
#define SB_OFF   (SW_OFF + 98)

__global__ __launch_bounds__(256) void k23(const float* __restrict__ w1d,
                                           const float* __restrict__ w2d,
                                           const float* __restrict__ bias)
{
    __shared__ float sbig[SB_OFF + 1];
    const int tid = threadIdx.x;

    if (blockIdx.x < B) {
        // ---- channel weight: mean -> conv1d(5, pad 2) -> sigmoid ----
        const int b = blockIdx.x;
        const int c = tid;
        float acc = 0.f;
        #pragma unroll
        for (int ht = 0; ht < NHWT; ++ht)
            acc += g_cpart[(b * NHWT + ht) * C + c];
        sbig[c] = acc * (1.0f / (float)HW);
        __syncthreads();
        float y = 0.f;
        #pragma unroll
        for (int k = 0; k < 5; ++k) {
            int cc = c - 2 + k;
            float m = (cc >= 0 && cc < C) ? sbig[cc] : 0.f;
            y += w1d[k] * m;
        }
        g_chw[b * C + c] = 1.0f / (1.0f + expf(-y));
    } else {
        // ---- spatial weight: pools -> conv2d(7x7, pad 3) -> sigmoid ----
        const int idx = blockIdx.x - B;
        const int b   = idx >> 2;
        const int r0  = (idx & 3) * 16;

        float* smax = sbig + SMAX_OFF;   // [22][72]
        float* savg = sbig + SAVG_OFF;   // [22][72]
        float* sw   = sbig + SW_OFF;     // [98]

        for (int i = tid; i < 22 * 70; i += 256) {
            int rr = i / 70, cc = i % 70;
            int gr = r0 - 3 + rr, gc = cc - 3;
            float mv = 0.f, av = 0.f;
            if (gr >= 0 && gr < W64 && gc >= 0 && gc < W64) {
                int gi = b * HW + gr * W64 + gc;
                mv = -CUDART_INF_F;
                #pragma unroll
                for (int r = 0; r < NCR; ++r) {
                    mv = fmaxf(mv, ((const float*)g_pmax[r])[gi]);
                    av += ((const float*)g_psum[r])[gi];
                }
                av *= (1.0f / (float)C);
            }
            smax[rr * 72 + cc] = mv;
            savg[rr * 72 + cc] = av;
        }
        if (tid < 98) sw[tid] = w2d[tid];
        if (tid == 0) sbig[SB_OFF] = bias[0];
        __syncthreads();

        float* __restrict__ sp = (float*)g_sp4;
        #pragma unroll
        for (int k = 0; k < 4; ++k) {
            int oi   = tid + k * 256;
            int orow = oi >> 6;
            int ocol = oi & 63;
            float acc = sbig[SB_OFF];
            #pragma unroll
            for (int kh = 0; kh < 7; ++kh) {
                #pragma unroll
                for (int kw = 0; kw < 7; ++kw) {
                    acc += sw[kh * 7 + kw]      * smax[(orow + kh) * 72 + ocol + kw];
                    acc += sw[49 + kh * 7 + kw] * savg[(orow + kh) * 72 + ocol + kw];
                }
            }
            sp[b * HW + (r0 + orow) * W64 + ocol] = 1.0f / (1.0f + expf(-acc));
        }
    }
}

// =====================================================================
// k4: out = x * (chw[b,c] + sp[b,hw] + 1), reversed traversal.
//     ONE CHANGE vs round 3: output stores are write-through (__stwt),
//     bypassing L2 allocation so x stays resident for the reads.
// =====================================================================
#define TOTAL4 (B * C * HW / 4)
__global__ __launch_bounds__(256) void k4_scale(const float4* __restrict__ x4,
                                                float4* __restrict__ out4)
{
    const int i4  = (TOTAL4 - 1) - (blockIdx.x * 256 + threadIdx.x);
    const int hw4 = i4 & 1023;
    const int bc  = i4 >> 10;
    const int b   = bc >> 8;

    const float  cw = g_chw[bc] + 1.0f;
    const float4 sp = g_sp4[b * 1024 + hw4];
    const float4 v  = x4[i4];

    float4 o;
    o.x = v.x * (cw + sp.x);
    o.y = v.y * (cw + sp.y);
    o.z = v.z * (cw + sp.z);
    o.w = v.w * (cw + sp.w);
    __stwt(&out4[i4], o);
}

// =====================================================================
extern "C" void kernel_launch(void* const* d_in, const int* in_sizes, int n_in,
                              void* d_out, int out_size)
{
    const float* x    = (const float*)d_in[0];  // [32,256,64,64]
    const float* w1d  = (const float*)d_in[1];  // [1,1,5]
    const float* w2d  = (const float*)d_in[2];  // [1,2,7,7]
    const float* bias = (const float*)d_in[3];  // [1]
    float* out = (float*)d_out;

    dim3 g1(NCR, NHWT, B);
    k1_reduce<<<g1, K1T>>>(x);
    k23<<<B + B * 4, 256>>>(w1d, w2d, bias);
    k4_scale<<<TOTAL4 / 256, 256>>>((const float4*)x, (float4*)out);
}

// round 11
// speedup vs baseline: 1.0881x; 1.0525x over previous
#include <cuda_runtime.h>
#include <math_constants.h>

// x [B=32, C=256, H=64, W=64] fp32
#define B    32
#define C    256
#define HW   4096
#define W64  64

// ---- k1 tiling (round-3 optimum; do not touch) ----
#define K1T    128             // threads/block
#define HWT    512             // hw floats per block tile (128 float4)
#define NHWT   (HW / HWT)      // 8
#define CR     64              // channels per block
#define NCR    (C / CR)        // 4
#define CHUNK  4
#define NCHUNK (CR / CHUNK)    // 16

// ---- scratch (device globals; allocation-free) ----
__device__ float  g_cpart[B * NHWT * C];     // per-(b,c,hw-tile) partial sums
__device__ float4 g_pmax[NCR][B * HW / 4];   // per-c-range max partials
__device__ float4 g_psum[NCR][B * HW / 4];   // per-c-range sum partials
__device__ float  g_chw[B * C];              // channel weight
__device__ float4 g_sp4[B * HW / 4];         // spatial weight

// =====================================================================
// k1: single sweep over x. block=(cr,ht,b), 1024 CTAs.
// Register-prefetched 4-channel chunks; smem transpose for per-c sums.
// =====================================================================
__global__ __launch_bounds__(K1T) void k1_reduce(const float* __restrict__ x)
{
    const int cr   = blockIdx.x;
    const int ht   = blockIdx.y;
    const int b    = blockIdx.z;
    const int tid  = threadIdx.x;
    const int warp = tid >> 5;
    const int lane = tid & 31;

    __shared__ float sbuf[2][CHUNK][K1T];

    const float4* __restrict__ xp =
        (const float4*)x + ((long)(b * C + cr * CR) * HW + ht * HWT) / 4 + tid;

    float4 mx = make_float4(-CUDART_INF_F, -CUDART_INF_F, -CUDART_INF_F, -CUDART_INF_F);
    float4 sm = make_float4(0.f, 0.f, 0.f, 0.f);

    float4 p[CHUNK];
    #pragma unroll
    for (int j = 0; j < CHUNK; ++j) p[j] = xp[j * (HW / 4)];

    #pragma unroll 2
    for (int ch = 0; ch < NCHUNK; ++ch) {
        float4 v[CHUNK];
        #pragma unroll
        for (int j = 0; j < CHUNK; ++j) v[j] = p[j];

        // stage per-thread channel sums, then kick off next chunk's loads
        float (*sb)[K1T] = sbuf[ch & 1];
        #pragma unroll
        for (int j = 0; j < CHUNK; ++j)
            sb[j][tid] = (v[j].x + v[j].y) + (v[j].z + v[j].w);

        if (ch + 1 < NCHUNK) {
            #pragma unroll
            for (int j = 0; j < CHUNK; ++j)
                p[j] = xp[((ch + 1) * CHUNK + j) * (HW / 4)];
        }

        #pragma unroll
        for (int j = 0; j < CHUNK; ++j) {
            mx.x = fmaxf(mx.x, v[j].x); mx.y = fmaxf(mx.y, v[j].y);
            mx.z = fmaxf(mx.z, v[j].z); mx.w = fmaxf(mx.w, v[j].w);
            sm.x += v[j].x; sm.y += v[j].y; sm.z += v[j].z; sm.w += v[j].w;
        }

        __syncthreads();
        // warp w reduces channel ch*4+w over all 128 threads (stride-32: conflict-free)
        float r = (sb[warp][lane]      + sb[warp][lane + 32])
                + (sb[warp][lane + 64] + sb[warp][lane + 96]);
        r += __shfl_xor_sync(0xffffffffu, r, 16);
        r += __shfl_xor_sync(0xffffffffu, r, 8);
        r += __shfl_xor_sync(0xffffffffu, r, 4);
        r += __shfl_xor_sync(0xffffffffu, r, 2);
        r += __shfl_xor_sync(0xffffffffu, r, 1);
        if (lane == 0)
            g_cpart[(b * NHWT + ht) * C + cr * CR + ch * CHUNK + warp] = r;
    }

    const int o = b * (HW / 4) + ht * (HWT / 4) + tid;
    g_pmax[cr][o] = mx;
    g_psum[cr][o] = sm;
}

// =====================================================================
// k23: fused channel-weight (blocks 0..31) and spatial-weight (32..159).
// =====================================================================
#define SMAX_OFF 0
#define SAVG_OFF (22 * 72)
#define SW_OFF   (2 * 22 * 72)
#define SB_OFF   (SW_OFF + 98)

__global__ __launch_bounds__(256) void k23(const float* __restrict__ w1d,
                                           const float* __restrict__ w2d,
                                           const float* __restrict__ bias)
{
    __shared__ float sbig[SB_OFF + 1];
    const int tid = threadIdx.x;

    if (blockIdx.x < B) {
        // ---- channel weight: mean -> conv1d(5, pad 2) -> sigmoid ----
        const int b = blockIdx.x;
        const int c = tid;
        float acc = 0.f;
        #pragma unroll
        for (int ht = 0; ht < NHWT; ++ht)
            acc += g_cpart[(b * NHWT + ht) * C + c];
        sbig[c] = acc * (1.0f / (float)HW);
        __syncthreads();
        float y = 0.f;
        #pragma unroll
        for (int k = 0; k < 5; ++k) {
            int cc = c - 2 + k;
            float m = (cc >= 0 && cc < C) ? sbig[cc] : 0.f;
            y += w1d[k] * m;
        }
        g_chw[b * C + c] = 1.0f / (1.0f + expf(-y));
    } else {
        // ---- spatial weight: pools -> conv2d(7x7, pad 3) -> sigmoid ----
        const int idx = blockIdx.x - B;
        const int b   = idx >> 2;
        const int r0  = (idx & 3) * 16;

        float* smax = sbig + SMAX_OFF;   // [22][72]
        float* savg = sbig + SAVG_OFF;   // [22][72]
        float* sw   = sbig + SW_OFF;     // [98]

        for (int i = tid; i < 22 * 70; i += 256) {
            int rr = i / 70, cc = i % 70;
            int gr = r0 - 3 + rr, gc = cc - 3;
            float mv = 0.f, av = 0.f;
            if (gr >= 0 && gr < W64 && gc >= 0 && gc < W64) {
                int gi = b * HW + gr * W64 + gc;
                mv = -CUDART_INF_F;
                #pragma unroll
                for (int r = 0; r < NCR; ++r) {
                    mv = fmaxf(mv, ((const float*)g_pmax[r])[gi]);
                    av += ((const float*)g_psum[r])[gi];
                }
                av *= (1.0f / (float)C);
            }
            smax[rr * 72 + cc] = mv;
            savg[rr * 72 + cc] = av;
        }
        if (tid < 98) sw[tid] = w2d[tid];
        if (tid == 0) sbig[SB_OFF] = bias[0];
        __syncthreads();

        float* __restrict__ sp = (float*)g_sp4;
        #pragma unroll
        for (int k = 0; k < 4; ++k) {
            int oi   = tid + k * 256;
            int orow = oi >> 6;
            int ocol = oi & 63;
            float acc = sbig[SB_OFF];
            #pragma unroll
            for (int kh = 0; kh < 7; ++kh) {
                #pragma unroll
                for (int kw = 0; kw < 7; ++kw) {
                    acc += sw[kh * 7 + kw]      * smax[(orow + kh) * 72 + ocol + kw];
                    acc += sw[49 + kh * 7 + kw] * savg[(orow + kh) * 72 + ocol + kw];
                }
            }
            sp[b * HW + (r0 + orow) * W64 + ocol] = 1.0f / (1.0f + expf(-acc));
        }
    }
}

// =====================================================================
// k4: out = x * (chw[b,c] + sp[b,hw] + 1).
//     One CTA per (b,c) row: 512 threads x 2 float4 each (MLP=2),
//     uniform cw per block, reversed block order, evict-first stores.
// =====================================================================
__global__ __launch_bounds__(512) void k4_scale(const float4* __restrict__ x4,
                                                float4* __restrict__ out4)
{
    const int bc  = (B * C - 1) - blockIdx.x;      // reversed: tail of x first
    const int b   = bc >> 8;
    const int tid = threadIdx.x;

    const float cw = g_chw[bc] + 1.0f;

    const int rbase = bc * 1024;                   // this (b,c) row, in float4
    const int sbase = b * 1024;

    const float4 v0 = x4[rbase + tid];
    const float4 v1 = x4[rbase + tid + 512];
    const float4 s0 = g_sp4[sbase + tid];
    const float4 s1 = g_sp4[sbase + tid + 512];

    float4 o0, o1;
    o0.x = v0.x * (cw + s0.x);
    o0.y = v0.y * (cw + s0.y);
    o0.z = v0.z * (cw + s0.z);
    o0.w = v0.w * (cw + s0.w);
    o1.x = v1.x * (cw + s1.x);
    o1.y = v1.y * (cw + s1.y);
    o1.z = v1.z * (cw + s1.z);
    o1.w = v1.w * (cw + s1.w);

    __stcs(&out4[rbase + tid],       o0);
    __stcs(&out4[rbase + tid + 512], o1);
}

// =====================================================================
extern "C" void kernel_launch(void* const* d_in, const int* in_sizes, int n_in,
                              void* d_out, int out_size)
{
    const float* x    = (const float*)d_in[0];  // [32,256,64,64]
    const float* w1d  = (const float*)d_in[1];  // [1,1,5]
    const float* w2d  = (const float*)d_in[2];  // [1,2,7,7]
    const float* bias = (const float*)d_in[3];  // [1]
    float* out = (float*)d_out;

    dim3 g1(NCR, NHWT, B);
    k1_reduce<<<g1, K1T>>>(x);
    k23<<<B + B * 4, 256>>>(w1d, w2d, bias);
    k4_scale<<<B * C, 512>>>((const float4*)x, (float4*)out);
}